// round 3
// baseline (speedup 1.0000x reference)
#include <cuda_runtime.h>

#define T_STEPS 4096
#define RES     2048
#define NF      8
#define NO      8
#define GRID_B  128
#define BLOCK_B 288    // 8 matvec warps + 1 finalize warp
#define NC      16     // output columns per CTA

// Scratch (allocation-free rule: device globals)
__device__ float g_drive[T_STEPS * RES];            // 32 MB
__device__ float g_X[T_STEPS * RES];                // 32 MB
__device__ unsigned int g_flag[GRID_B];             // packed step flags

__device__ __forceinline__ unsigned long long ffma2(unsigned long long a,
                                                    unsigned long long b,
                                                    unsigned long long c) {
    unsigned long long d;
    asm("fma.rn.f32x2 %0, %1, %2, %3;" : "=l"(d) : "l"(a), "l"(b), "l"(c));
    return d;
}
__device__ __forceinline__ unsigned long long pack2(float x, float y) {
    unsigned long long d;
    asm("mov.b64 %0, {%1, %2};" : "=l"(d) : "f"(x), "f"(y));
    return d;
}

// ---------------------------------------------------------------------------
// Kernel A: drive[t][r] = win_bias[r] + inp[t] @ win_u[:, r]   (+ flag reset)
// ---------------------------------------------------------------------------
__global__ void drive_kernel(const float* __restrict__ inp,
                             const float* __restrict__ Win) {
    int t = blockIdx.y;
    int r = blockIdx.x * blockDim.x + threadIdx.x;
    if (blockIdx.x == 0 && blockIdx.y == 0 && threadIdx.x < GRID_B)
        g_flag[threadIdx.x] = 0u;
    float acc = Win[r];                       // bias row (Win[0])
#pragma unroll
    for (int f = 0; f < NF; f++)
        acc += inp[t * NF + f] * Win[(1 + f) * RES + r];
    g_drive[t * RES + r] = acc;
}

// ---------------------------------------------------------------------------
// Kernel B: persistent scan.
//   128 CTAs; each owns 16 output columns of W in registers.
//   Warps 0-7: matvec. lane: col = lane&15, half = lane>>4.
//     warp w covers rows [w*256,(w+1)*256); its sx slice is PRIVATE to it.
//   Warp 8: finalize (16 lanes): sred -> tanh -> x_{t+1} -> g_X + flag.
//     Keeps x_old in registers (no cross-warp smem dependency).
//   One __syncthreads per step; sred double-buffered by step parity.
// ---------------------------------------------------------------------------
__global__ void __launch_bounds__(BLOCK_B, 1)
scan_kernel(const float* __restrict__ W) {
    __shared__ float sx[RES];              // x_t, per-warp-private 256-slices
    __shared__ float sred[2][8 * NC];      // per-warp partials, double-buffered

    const int tid  = threadIdx.x;
    const int w    = tid >> 5;
    const int lane = tid & 31;
    const int cb   = blockIdx.x;
    const int cbj  = cb * NC;              // column base of this CTA

    const float dmp = 0.3f;
    const float omd = 1.0f - 0.3f;

    if (w < 8) {
        // ================= matvec warp =================
        const int col  = lane & 15;
        const int half = lane >> 4;
        const int jg   = cbj + col;
        const int i0   = w * 256 + half * 128;    // this lane's 128-row chunk

        // one-time: W slice (128 rows x 1 col) into registers
        unsigned long long wrA[32], wrB[32];
#pragma unroll
        for (int k = 0; k < 32; k++) {
            int i = i0 + 4 * k;
            wrA[k] = pack2(__ldg(&W[(size_t)i * RES + jg]),
                           __ldg(&W[(size_t)(i + 1) * RES + jg]));
            wrB[k] = pack2(__ldg(&W[(size_t)(i + 2) * RES + jg]),
                           __ldg(&W[(size_t)(i + 3) * RES + jg]));
        }

        // zero own sx slice (x_0 = 0)
        float4* sx4 = reinterpret_cast<float4*>(sx);
        sx4[w * 64 + lane]      = make_float4(0.f, 0.f, 0.f, 0.f);
        sx4[w * 64 + 32 + lane] = make_float4(0.f, 0.f, 0.f, 0.f);
        __syncwarp();

        const ulonglong2* sxu2 =
            reinterpret_cast<const ulonglong2*>(sx) + (w * 64 + half * 32);
        const unsigned int* fp = &g_flag[w * 16 + (lane & 15)];

        for (int t = 0; t < T_STEPS; t++) {
            // ---- matvec partial: 32 LDS.128 + 64 fma.f32x2, 4 chains
            unsigned long long a0 = 0ull, a1 = 0ull, a2 = 0ull, a3 = 0ull;
#pragma unroll
            for (int k = 0; k < 32; k += 2) {
                ulonglong2 x0 = sxu2[k];
                ulonglong2 x1 = sxu2[k + 1];
                a0 = ffma2(wrA[k],     x0.x, a0);
                a1 = ffma2(wrB[k],     x0.y, a1);
                a2 = ffma2(wrA[k + 1], x1.x, a2);
                a3 = ffma2(wrB[k + 1], x1.y, a3);
            }
            float2 f0 = *reinterpret_cast<float2*>(&a0);
            float2 f1 = *reinterpret_cast<float2*>(&a1);
            float2 f2 = *reinterpret_cast<float2*>(&a2);
            float2 f3 = *reinterpret_cast<float2*>(&a3);
            float s = ((f0.x + f0.y) + (f1.x + f1.y)) +
                      ((f2.x + f2.y) + (f3.x + f3.y));
            s += __shfl_down_sync(0xffffffffu, s, 16);     // fold halves
            if (half == 0) sred[t & 1][w * NC + col] = s;

            __syncthreads();                                // the step barrier
            if (t == T_STEPS - 1) break;

            // ---- poll own 16 producers (coalesced, volatile), then fence
            {
                unsigned target = (unsigned)(t + 1);
                unsigned v;
                bool ok;
                do {
                    asm volatile("ld.volatile.global.u32 %0, [%1];"
                                 : "=r"(v) : "l"(fp));
                    ok = __all_sync(0xffffffffu, v >= target);
                } while (!ok);
                asm volatile("fence.acq_rel.gpu;" ::: "memory");
            }

            // ---- reload own 256-float slice of x_{t+1}
            const float4* src =
                reinterpret_cast<const float4*>(&g_X[(size_t)t * RES]) + w * 64;
            float4 v0 = __ldcg(&src[lane]);
            float4 v1 = __ldcg(&src[lane + 32]);
            sx4[w * 64 + lane]      = v0;
            sx4[w * 64 + 32 + lane] = v1;
            __syncwarp();
        }
    } else {
        // ================= finalize warp (warp 8) =================
        float xold = 0.0f;
        float drv  = (lane < NC) ? g_drive[cbj + lane] : 0.0f;   // t = 0

        for (int t = 0; t < T_STEPS; t++) {
            __syncthreads();                                // the step barrier

            float xn = 0.0f;
            if (lane < NC) {
                float tot = 0.0f;
#pragma unroll
                for (int ww = 0; ww < 8; ww++)
                    tot += sred[t & 1][ww * NC + lane];
                xn = omd * xold + dmp * tanhf(drv + tot);
                xold = xn;
                g_X[(size_t)t * RES + cbj + lane] = xn;
            }
            __syncwarp();
            if (lane == 0 && t < T_STEPS - 1) {
                __threadfence();                            // order x before flag
                asm volatile("st.relaxed.gpu.u32 [%0], %1;"
                             :: "l"(&g_flag[cb]), "r"((unsigned)(t + 1))
                             : "memory");
            }
            // prefetch next drive (latency hidden behind next barrier wait)
            if (lane < NC && t < T_STEPS - 1)
                drv = g_drive[(size_t)(t + 1) * RES + cbj + lane];
        }
    }
}

// ---------------------------------------------------------------------------
// Kernel C: Y[t] = wout_bias + inp[t] @ wout_u + x_{t+1} @ wout_x
// ---------------------------------------------------------------------------
__global__ void readout_kernel(const float* __restrict__ inp,
                               const float* __restrict__ Wout,
                               float* __restrict__ out) {
    const int w    = threadIdx.x >> 5;
    const int lane = threadIdx.x & 31;
    const int t    = blockIdx.x * 8 + w;

    float acc[NO];
#pragma unroll
    for (int o = 0; o < NO; o++) acc[o] = 0.0f;

    const float* xrow = &g_X[(size_t)t * RES];
    for (int it = 0; it < RES / 32; it++) {
        int r = it * 32 + lane;
        float xv = xrow[r];
        const float4* wrow =
            reinterpret_cast<const float4*>(&Wout[(size_t)(1 + NF + r) * NO]);
        float4 wa = wrow[0], wb = wrow[1];
        acc[0] += xv * wa.x; acc[1] += xv * wa.y;
        acc[2] += xv * wa.z; acc[3] += xv * wa.w;
        acc[4] += xv * wb.x; acc[5] += xv * wb.y;
        acc[6] += xv * wb.z; acc[7] += xv * wb.w;
    }
#pragma unroll
    for (int o = 0; o < NO; o++) {
#pragma unroll
        for (int sft = 16; sft > 0; sft >>= 1)
            acc[o] += __shfl_down_sync(0xffffffffu, acc[o], sft);
    }
    if (lane == 0) {
#pragma unroll
        for (int o = 0; o < NO; o++) {
            float y = Wout[o];
#pragma unroll
            for (int f = 0; f < NF; f++)
                y += inp[t * NF + f] * Wout[(1 + f) * NO + o];
            out[t * NO + o] = y + acc[o];
        }
    }
}

// ---------------------------------------------------------------------------
extern "C" void kernel_launch(void* const* d_in, const int* in_sizes, int n_in,
                              void* d_out, int out_size) {
    const float* inp  = (const float*)d_in[0];   // (4096, 8)
    const float* Win  = (const float*)d_in[1];   // (9, 2048)
    const float* W    = (const float*)d_in[2];   // (2048, 2048)
    const float* Wout = (const float*)d_in[3];   // (2057, 8)
    float* out = (float*)d_out;                  // (4096, 8) fp32

    dim3 ga(RES / 256, T_STEPS);
    drive_kernel<<<ga, 256>>>(inp, Win);
    scan_kernel<<<GRID_B, BLOCK_B>>>(W);
    readout_kernel<<<T_STEPS / 8, 256>>>(inp, Wout, out);
}

// round 4
// speedup vs baseline: 1.7688x; 1.7688x over previous
#include <cuda_runtime.h>

#define T_STEPS 4096
#define RES     2048
#define NF      8
#define NO      8
#define GRID_B  128
#define BLOCK_B 256
#define NC      16     // output columns per CTA

// Scratch (allocation-free rule: device globals)
__device__ float g_drive[T_STEPS * RES];            // 32 MB
__device__ float g_X[T_STEPS * RES];                // 32 MB
__device__ unsigned int g_flag[GRID_B];             // packed per-CTA step flags

__device__ __forceinline__ unsigned long long ffma2(unsigned long long a,
                                                    unsigned long long b,
                                                    unsigned long long c) {
    unsigned long long d;
    asm("fma.rn.f32x2 %0, %1, %2, %3;" : "=l"(d) : "l"(a), "l"(b), "l"(c));
    return d;
}
__device__ __forceinline__ unsigned long long pack2(float x, float y) {
    unsigned long long d;
    asm("mov.b64 %0, {%1, %2};" : "=l"(d) : "f"(x), "f"(y));
    return d;
}
__device__ __forceinline__ unsigned ld_relaxed(const unsigned int* p) {
    unsigned v;
    asm volatile("ld.relaxed.gpu.global.u32 %0, [%1];" : "=r"(v) : "l"(p));
    return v;
}

// ---------------------------------------------------------------------------
// Kernel A: drive[t][r] = win_bias[r] + inp[t] @ win_u[:, r]   (+ flag reset)
// ---------------------------------------------------------------------------
__global__ void drive_kernel(const float* __restrict__ inp,
                             const float* __restrict__ Win) {
    int t = blockIdx.y;
    int r = blockIdx.x * blockDim.x + threadIdx.x;
    if (blockIdx.x == 0 && blockIdx.y == 0 && threadIdx.x < GRID_B)
        g_flag[threadIdx.x] = 0u;
    float acc = Win[r];                       // bias row (Win[0])
#pragma unroll
    for (int f = 0; f < NF; f++)
        acc += inp[t * NF + f] * Win[(1 + f) * RES + r];
    g_drive[t * RES + r] = acc;
}

// ---------------------------------------------------------------------------
// Kernel B: persistent scan. 128 CTAs x 256 thr; each CTA owns 16 columns of
// W in registers (warp w, lane: col=lane&15, half=lane>>4 -> 128-row chunk).
// Barrier: 128 independent relaxed flag stores (NO same-address atomic);
// warp 1 aggregates with 4 coalesced relaxed loads + one acq_rel fence.
// Warp 0 finalizes (tanh, x update) concurrently with warp 1's polling.
// ---------------------------------------------------------------------------
__global__ void __launch_bounds__(BLOCK_B, 1)
scan_kernel(const float* __restrict__ W) {
    __shared__ float sx[RES];              // x_t; warp-private 256-slices
    __shared__ float sred[8][NC];          // per-warp partials

    const int tid  = threadIdx.x;
    const int w    = tid >> 5;
    const int lane = tid & 31;
    const int col  = lane & 15;
    const int half = lane >> 4;
    const int cb   = blockIdx.x;
    const int cbj  = cb * NC;              // column base of this CTA
    const int jg   = cbj + col;            // global output column
    const int i0   = w * 256 + half * 128; // this lane's 128-row chunk

    const float dmp = 0.3f;
    const float omd = 1.0f - 0.3f;

    // --- one-time: W slice (128 rows x 1 col) into registers
    unsigned long long wrA[32], wrB[32];
#pragma unroll
    for (int k = 0; k < 32; k++) {
        int i = i0 + 4 * k;
        wrA[k] = pack2(__ldg(&W[(size_t)i * RES + jg]),
                       __ldg(&W[(size_t)(i + 1) * RES + jg]));
        wrB[k] = pack2(__ldg(&W[(size_t)(i + 2) * RES + jg]),
                       __ldg(&W[(size_t)(i + 3) * RES + jg]));
    }

    // x_0 = 0
    float4* sx4 = reinterpret_cast<float4*>(sx);
    sx4[w * 64 + lane]      = make_float4(0.f, 0.f, 0.f, 0.f);
    sx4[w * 64 + 32 + lane] = make_float4(0.f, 0.f, 0.f, 0.f);
    __syncthreads();

    const ulonglong2* sxu2 =
        reinterpret_cast<const ulonglong2*>(sx) + (w * 64 + half * 32);

    float xold = 0.0f;   // warp 0, lanes 0-15: running x for own column

    for (int t = 0; t < T_STEPS; t++) {
        // finalize lanes: issue drive load early (resolves during matvec)
        float drv = 0.0f;
        if (w == 0 && lane < NC) drv = __ldcg(&g_drive[(size_t)t * RES + cbj + lane]);

        // ---- matvec partial: 32 broadcast LDS.128 + 64 fma.f32x2, 4 chains
        unsigned long long a0 = 0ull, a1 = 0ull, a2 = 0ull, a3 = 0ull;
#pragma unroll
        for (int k = 0; k < 32; k += 2) {
            ulonglong2 x0 = sxu2[k];
            ulonglong2 x1 = sxu2[k + 1];
            a0 = ffma2(wrA[k],     x0.x, a0);
            a1 = ffma2(wrB[k],     x0.y, a1);
            a2 = ffma2(wrA[k + 1], x1.x, a2);
            a3 = ffma2(wrB[k + 1], x1.y, a3);
        }
        float2 f0 = *reinterpret_cast<float2*>(&a0);
        float2 f1 = *reinterpret_cast<float2*>(&a1);
        float2 f2 = *reinterpret_cast<float2*>(&a2);
        float2 f3 = *reinterpret_cast<float2*>(&a3);
        float s = ((f0.x + f0.y) + (f1.x + f1.y)) +
                  ((f2.x + f2.y) + (f3.x + f3.y));
        s += __shfl_down_sync(0xffffffffu, s, 16);     // fold halves
        if (half == 0) sred[w][col] = s;

        __syncthreads();                                // bar 1

        if (w == 0) {
            // ---- finalize 16 columns -> x_{t+1} -> g_X, then release flag
            if (lane < NC) {
                float tot = 0.0f;
#pragma unroll
                for (int ww = 0; ww < 8; ww++) tot += sred[ww][lane];
                float xn = omd * xold + dmp * tanhf(drv + tot);
                xold = xn;
                g_X[(size_t)t * RES + cbj + lane] = xn;
            }
            if (t < T_STEPS - 1) {
                __syncwarp();                           // order 16 STGs in-warp
                if (lane == 0)
                    asm volatile("st.release.gpu.global.u32 [%0], %1;"
                                 :: "l"(&g_flag[cb]), "r"((unsigned)(t + 1))
                                 : "memory");
            }
        } else if (w == 1 && t < T_STEPS - 1) {
            // ---- poll all 128 flags: 4 coalesced relaxed loads per lane
            const unsigned target = (unsigned)(t + 1);
            for (;;) {
                unsigned v0 = ld_relaxed(&g_flag[lane]);
                unsigned v1 = ld_relaxed(&g_flag[lane + 32]);
                unsigned v2 = ld_relaxed(&g_flag[lane + 64]);
                unsigned v3 = ld_relaxed(&g_flag[lane + 96]);
                bool ok = (v0 >= target) & (v1 >= target) &
                          (v2 >= target) & (v3 >= target);
                if (__all_sync(0xffffffffu, ok)) break;
            }
            asm volatile("fence.acq_rel.gpu;" ::: "memory");  // one per CTA/step
        }

        if (t == T_STEPS - 1) break;
        __syncthreads();                                // bar 2

        // ---- reload own warp-private 256-float slice of x_{t+1}
        const float4* src =
            reinterpret_cast<const float4*>(&g_X[(size_t)t * RES]) + w * 64;
        float4 v0 = __ldcg(&src[lane]);
        float4 v1 = __ldcg(&src[lane + 32]);
        sx4[w * 64 + lane]      = v0;
        sx4[w * 64 + 32 + lane] = v1;
        __syncwarp();
    }
}

// ---------------------------------------------------------------------------
// Kernel C: Y[t] = wout_bias + inp[t] @ wout_u + x_{t+1} @ wout_x
// ---------------------------------------------------------------------------
__global__ void readout_kernel(const float* __restrict__ inp,
                               const float* __restrict__ Wout,
                               float* __restrict__ out) {
    const int w    = threadIdx.x >> 5;
    const int lane = threadIdx.x & 31;
    const int t    = blockIdx.x * 8 + w;

    float acc[NO];
#pragma unroll
    for (int o = 0; o < NO; o++) acc[o] = 0.0f;

    const float* xrow = &g_X[(size_t)t * RES];
    for (int it = 0; it < RES / 32; it++) {
        int r = it * 32 + lane;
        float xv = xrow[r];
        const float4* wrow =
            reinterpret_cast<const float4*>(&Wout[(size_t)(1 + NF + r) * NO]);
        float4 wa = wrow[0], wb = wrow[1];
        acc[0] += xv * wa.x; acc[1] += xv * wa.y;
        acc[2] += xv * wa.z; acc[3] += xv * wa.w;
        acc[4] += xv * wb.x; acc[5] += xv * wb.y;
        acc[6] += xv * wb.z; acc[7] += xv * wb.w;
    }
#pragma unroll
    for (int o = 0; o < NO; o++) {
#pragma unroll
        for (int sft = 16; sft > 0; sft >>= 1)
            acc[o] += __shfl_down_sync(0xffffffffu, acc[o], sft);
    }
    if (lane == 0) {
#pragma unroll
        for (int o = 0; o < NO; o++) {
            float y = Wout[o];
#pragma unroll
            for (int f = 0; f < NF; f++)
                y += inp[t * NF + f] * Wout[(1 + f) * NO + o];
            out[t * NO + o] = y + acc[o];
        }
    }
}

// ---------------------------------------------------------------------------
extern "C" void kernel_launch(void* const* d_in, const int* in_sizes, int n_in,
                              void* d_out, int out_size) {
    const float* inp  = (const float*)d_in[0];   // (4096, 8)
    const float* Win  = (const float*)d_in[1];   // (9, 2048)
    const float* W    = (const float*)d_in[2];   // (2048, 2048)
    const float* Wout = (const float*)d_in[3];   // (2057, 8)
    float* out = (float*)d_out;                  // (4096, 8) fp32

    dim3 ga(RES / 256, T_STEPS);
    drive_kernel<<<ga, 256>>>(inp, Win);
    scan_kernel<<<GRID_B, BLOCK_B>>>(W);
    readout_kernel<<<T_STEPS / 8, 256>>>(inp, Wout, out);
}